// round 5
// baseline (speedup 1.0000x reference)
#include <cuda_runtime.h>

#define N_ATOMS   100000
#define IN_F      512
#define HID       512
#define OUT_F     256
#define EMB_DIM   16
#define N_ROUTED  6
#define N_SHARED  2

#define TM   64      // atoms per block tile
#define KC   32      // k-chunk for weight streaming
#define HC   128     // hidden chunk
#define NT   256     // threads per block
#define WPAD 36      // padded row stride (floats) for weight smem tiles

// Scratch (device globals — no allocation allowed)
__device__ int   g_top_idx[N_ATOMS * 2];
__device__ float g_top_w[N_ATOMS * 2];
__device__ int   g_count[N_ROUTED];
__device__ int   g_offset[N_ROUTED];
__device__ int   g_cursor[N_ROUTED];
__device__ int   g_list[N_ATOMS * 2];
__device__ float g_gate[N_ATOMS * 2];

// smem: Xs[64][512] + Hs[64][128] + Ws[256][36]
#define SMEM_FLOATS (TM * IN_F + TM * HC + 256 * WPAD)
#define SMEM_BYTES  (SMEM_FLOATS * 4)

__global__ void zero_meta_kernel() {
    int t = threadIdx.x;
    if (t < N_ROUTED) { g_count[t] = 0; g_cursor[t] = 0; }
}

__global__ void router_kernel(const float* __restrict__ emb,
                              const int* __restrict__ sp,
                              const float* __restrict__ Wr) {
    int i = blockIdx.x * blockDim.x + threadIdx.x;
    if (i >= N_ATOMS) return;
    int z = sp[i];
    float u[EMB_DIM];
#pragma unroll
    for (int d = 0; d < EMB_DIM; d++) {
        float v = emb[z * EMB_DIM + d];
        u[d] = v / (1.f + expf(-v));      // silu
    }
    float p[N_ROUTED];
    float mx = -3.4e38f;
#pragma unroll
    for (int e = 0; e < N_ROUTED; e++) {
        float s = 0.f;
#pragma unroll
        for (int d = 0; d < EMB_DIM; d++) s += u[d] * Wr[e * EMB_DIM + d];
        p[e] = s;
        if (s > mx) mx = s;
    }
    float sum = 0.f;
#pragma unroll
    for (int e = 0; e < N_ROUTED; e++) { p[e] = expf(p[e] - mx); sum += p[e]; }
    float inv = 1.f / sum;
    // top-2 (strict > reproduces jax top_k tie-break: lowest index wins)
    int i0 = 0; float p0 = p[0];
#pragma unroll
    for (int e = 1; e < N_ROUTED; e++) if (p[e] > p0) { p0 = p[e]; i0 = e; }
    int i1 = -1; float p1 = -3.4e38f;
#pragma unroll
    for (int e = 0; e < N_ROUTED; e++)
        if (e != i0 && p[e] > p1) { p1 = p[e]; i1 = e; }

    g_top_idx[2 * i]     = i0;  g_top_w[2 * i]     = p0 * inv;
    g_top_idx[2 * i + 1] = i1;  g_top_w[2 * i + 1] = p1 * inv;
    atomicAdd(&g_count[i0], 1);
    atomicAdd(&g_count[i1], 1);
}

__global__ void scan_kernel() {
    int acc = 0;
    for (int e = 0; e < N_ROUTED; e++) { g_offset[e] = acc; acc += g_count[e]; }
}

__global__ void scatter_kernel() {
    int i = blockIdx.x * blockDim.x + threadIdx.x;
    if (i >= N_ATOMS) return;
#pragma unroll
    for (int j = 0; j < 2; j++) {
        int e = g_top_idx[2 * i + j];
        int pos = g_offset[e] + atomicAdd(&g_cursor[e], 1);
        g_list[pos] = i;
        g_gate[pos] = g_top_w[2 * i + j];
    }
}

__global__ void zero_out_kernel(float4* __restrict__ out, int n4) {
    int i = blockIdx.x * blockDim.x + threadIdx.x;
    if (i < n4) out[i] = make_float4(0.f, 0.f, 0.f, 0.f);
}

// One block = 64 atoms of one expert-slot. slots 0..5 = routed, 6..7 = shared.
// Fused: H = silu(X W1^T + b1) computed in 4 chunks of 128 hidden units,
// each chunk immediately consumed by GEMM2 accumulation (H never leaves smem).
__global__ __launch_bounds__(NT, 1) void moe_kernel(
    const float* __restrict__ feat,
    const float* __restrict__ rW1, const float* __restrict__ rb1,
    const float* __restrict__ rW2, const float* __restrict__ rb2,
    const float* __restrict__ sW1, const float* __restrict__ sb1,
    const float* __restrict__ sW2, const float* __restrict__ sb2,
    float* __restrict__ out)
{
    extern __shared__ float smem[];
    float* Xs = smem;                 // [TM][IN_F]
    float* Hs = Xs + TM * IN_F;       // [TM][HC]
    float* Ws = Hs + TM * HC;         // [<=256][WPAD]
    __shared__ int   s_atom[TM];
    __shared__ float s_gate[TM];

    const int slot = blockIdx.y;
    const int tile = blockIdx.x;
    const int tid  = threadIdx.x;

    const float *W1, *B1, *W2, *B2;
    int nrows, base;
    const bool routed = (slot < N_ROUTED);
    if (routed) {
        const int cnt   = g_count[slot];
        const int start = tile * TM;
        if (start >= cnt) return;
        nrows = min(TM, cnt - start);
        base  = g_offset[slot] + start;
        W1 = rW1 + (size_t)slot * HID * IN_F;   B1 = rb1 + slot * HID;
        W2 = rW2 + (size_t)slot * OUT_F * HID;  B2 = rb2 + slot * OUT_F;
    } else {
        const int s     = slot - N_ROUTED;
        const int start = tile * TM;
        if (start >= N_ATOMS) return;
        nrows = min(TM, N_ATOMS - start);
        base  = start;
        W1 = sW1 + (size_t)s * HID * IN_F;      B1 = sb1 + s * HID;
        W2 = sW2 + (size_t)s * OUT_F * HID;     B2 = sb2 + s * OUT_F;
    }

    if (tid < TM) {
        if (tid < nrows) {
            if (routed) { s_atom[tid] = g_list[base + tid]; s_gate[tid] = g_gate[base + tid]; }
            else        { s_atom[tid] = base + tid;         s_gate[tid] = 1.f; }
        } else { s_atom[tid] = 0; s_gate[tid] = 0.f; }
    }
    __syncthreads();

    // Gather X tile into smem (zero-fill padded rows)
#pragma unroll
    for (int it = 0; it < (TM * IN_F / 4) / NT; it++) {
        int idx = tid + it * NT;          // float4 index, 0..8191
        int m = idx >> 7;                 // 128 float4 per row
        int c = idx & 127;
        float4 v = make_float4(0.f, 0.f, 0.f, 0.f);
        if (m < nrows)
            v = *(const float4*)(feat + (size_t)s_atom[m] * IN_F + (c << 2));
        *(float4*)(Xs + m * IN_F + (c << 2)) = v;
    }
    __syncthreads();

    const int tx = tid & 15;   // h / o dimension
    const int ty = tid >> 4;   // m dimension

    float acc2[4][16];
#pragma unroll
    for (int ii = 0; ii < 4; ii++)
#pragma unroll
        for (int jj = 0; jj < 16; jj++) acc2[ii][jj] = 0.f;

    for (int ch = 0; ch < HID / HC; ch++) {
        // ---------- GEMM1: Hc[64,128] = silu(X[64,512] @ W1c^T + b1) ----------
        float acc1[4][8];
#pragma unroll
        for (int ii = 0; ii < 4; ii++)
#pragma unroll
            for (int jj = 0; jj < 8; jj++) acc1[ii][jj] = 0.f;

        for (int kc = 0; kc < IN_F; kc += KC) {
            // stream W1 chunk: 128 rows x 32 cols
#pragma unroll
            for (int it = 0; it < 4; it++) {
                int idx = tid + it * NT;      // 0..1023
                int r = idx >> 3, c = idx & 7;
                float4 v = *(const float4*)(W1 + (size_t)(ch * HC + r) * IN_F + kc + (c << 2));
                *(float4*)(Ws + r * WPAD + (c << 2)) = v;
            }
            __syncthreads();
#pragma unroll
            for (int kk = 0; kk < KC; kk += 4) {
                float4 a[4];
#pragma unroll
                for (int ii = 0; ii < 4; ii++)
                    a[ii] = *(const float4*)(Xs + (ty + 16 * ii) * IN_F + kc + kk);
#pragma unroll
                for (int jj = 0; jj < 8; jj++) {
                    float4 b = *(const float4*)(Ws + (tx + 16 * jj) * WPAD + kk);
#pragma unroll
                    for (int ii = 0; ii < 4; ii++)
                        acc1[ii][jj] += a[ii].x * b.x + a[ii].y * b.y
                                      + a[ii].z * b.z + a[ii].w * b.w;
                }
            }
            __syncthreads();
        }
        // bias + silu -> Hs
#pragma unroll
        for (int jj = 0; jj < 8; jj++) {
            int h = tx + 16 * jj;
            float bb = B1[ch * HC + h];
#pragma unroll
            for (int ii = 0; ii < 4; ii++) {
                float v = acc1[ii][jj] + bb;
                v = v / (1.f + __expf(-v));
                Hs[(ty + 16 * ii) * HC + h] = v;
            }
        }
        __syncthreads();

        // ---------- GEMM2: Out[64,256] += Hc[64,128] @ W2c^T ----------
        for (int hk = 0; hk < HC; hk += KC) {
#pragma unroll
            for (int it = 0; it < 8; it++) {
                int idx = tid + it * NT;      // 0..2047
                int r = idx >> 3, c = idx & 7;
                float4 v = *(const float4*)(W2 + (size_t)r * HID + ch * HC + hk + (c << 2));
                *(float4*)(Ws + r * WPAD + (c << 2)) = v;
            }
            __syncthreads();
#pragma unroll
            for (int hh = 0; hh < KC; hh += 4) {
                float4 a[4];
#pragma unroll
                for (int ii = 0; ii < 4; ii++)
                    a[ii] = *(const float4*)(Hs + (ty + 16 * ii) * HC + hk + hh);
#pragma unroll
                for (int jj = 0; jj < 16; jj++) {
                    float4 b = *(const float4*)(Ws + (tx + 16 * jj) * WPAD + hh);
#pragma unroll
                    for (int ii = 0; ii < 4; ii++)
                        acc2[ii][jj] += a[ii].x * b.x + a[ii].y * b.y
                                      + a[ii].z * b.z + a[ii].w * b.w;
                }
            }
            __syncthreads();
        }
    }

    // epilogue: gate * (out + b2), accumulate into global output
#pragma unroll
    for (int ii = 0; ii < 4; ii++) {
        int m = ty + 16 * ii;
        if (m < nrows) {
            float g = s_gate[m];
            float* orow = out + (size_t)s_atom[m] * OUT_F;
#pragma unroll
            for (int jj = 0; jj < 16; jj++) {
                int o = tx + 16 * jj;
                atomicAdd(orow + o, g * (acc2[ii][jj] + B2[o]));
            }
        }
    }
}

extern "C" void kernel_launch(void* const* d_in, const int* in_sizes, int n_in,
                              void* d_out, int out_size) {
    const float* feat = (const float*)d_in[0];
    const int*   sp   = (const int*)  d_in[1];
    const float* emb  = (const float*)d_in[2];
    const float* Wr   = (const float*)d_in[3];
    const float* rW1  = (const float*)d_in[4];
    const float* rb1  = (const float*)d_in[5];
    const float* rW2  = (const float*)d_in[6];
    const float* rb2  = (const float*)d_in[7];
    const float* sW1  = (const float*)d_in[8];
    const float* sb1  = (const float*)d_in[9];
    const float* sW2  = (const float*)d_in[10];
    const float* sb2  = (const float*)d_in[11];
    float* out = (float*)d_out;

    cudaFuncSetAttribute(moe_kernel,
                         cudaFuncAttributeMaxDynamicSharedMemorySize, SMEM_BYTES);

    zero_meta_kernel<<<1, 32>>>();
    router_kernel<<<(N_ATOMS + 255) / 256, 256>>>(emb, sp, Wr);
    scan_kernel<<<1, 1>>>();
    scatter_kernel<<<(N_ATOMS + 255) / 256, 256>>>();

    const int n4 = N_ATOMS * OUT_F / 4;
    zero_out_kernel<<<(n4 + 255) / 256, 256>>>((float4*)out, n4);

    dim3 grid((N_ATOMS + TM - 1) / TM, N_ROUTED + N_SHARED);
    moe_kernel<<<grid, NT, SMEM_BYTES>>>(feat, rW1, rb1, rW2, rb2,
                                         sW1, sb1, sW2, sb2, out);
}